// round 5
// baseline (speedup 1.0000x reference)
#include <cuda_runtime.h>
#include <cuda_bf16.h>
#include <math.h>
#include <stdint.h>

#define BATCH 32
#define SEQT  512
#define IND   512
#define UNITS 1024
#define GDIM  4096              // 4*UNITS
#define MROWS (BATCH*SEQT)      // 16384

// persistent recurrence decomposition
#define KS_SPLIT 4              // K split over blocks
#define KCH      256            // K elements per block
#define GTILE    128            // g rows per block
#define NBLK     128            // 32 g-tiles * 4 K-splits

// SMEM: A fragments [term2][mt8][ks16][lane32][4xb32] = 128KB
//       B fragments [term2][nt4][ks16][lane32][2xb32] =  32KB
#define SM_A      0
#define SM_ATERM  65536
#define SM_B      131072
#define SM_BTERM  16384
#define SM_TOTAL  163840

// -------------------- device globals (no runtime alloc) --------------------
__device__ float         g_xg[(size_t)SEQT * BATCH * GDIM];   // [T][B][4U]
__device__ uint32_t      g_wfrag[(size_t)NBLK * 32768];       // frag-ordered Wh, 16MB
__device__ __nv_bfloat16 g_h_hi[BATCH * UNITS];               // h split [b][k]
__device__ __nv_bfloat16 g_h_lo[BATCH * UNITS];
__device__ float         g_c[BATCH * UNITS];
__device__ float         g_part[(size_t)KS_SPLIT * GDIM * BATCH]; // [ks][g][b]
__device__ unsigned int  g_bar_count;
__device__ unsigned int  g_bar_release;

// -------------------- helpers --------------------
__device__ __forceinline__ uint32_t smem_u32(const void* p) {
    uint32_t a;
    asm("{ .reg .u64 t; cvta.to.shared.u64 t, %1; cvt.u32.u64 %0, t; }"
        : "=r"(a) : "l"(p));
    return a;
}
__device__ __forceinline__ unsigned int bar_arrive_add(unsigned int* p) {
    unsigned int old;
    asm volatile("atom.add.release.gpu.global.u32 %0, [%1], 1;"
                 : "=r"(old) : "l"(p) : "memory");
    return old;
}
__device__ __forceinline__ void st_release(unsigned int* p, unsigned int v) {
    asm volatile("st.release.gpu.global.u32 [%0], %1;" :: "l"(p), "r"(v) : "memory");
}
__device__ __forceinline__ unsigned int ld_acquire(unsigned int* p) {
    unsigned int v;
    asm volatile("ld.acquire.gpu.global.u32 %0, [%1];" : "=r"(v) : "l"(p) : "memory");
    return v;
}
// grid barrier; epoch strictly increases within a launch
__device__ __forceinline__ void grid_bar(int tid, unsigned int epoch) {
    __syncthreads();
    if (tid == 0) {
        unsigned int old = bar_arrive_add(&g_bar_count);
        if (old == NBLK - 1) {
            g_bar_count = 0;
            asm volatile("fence.acq_rel.gpu;" ::: "memory");
            st_release(&g_bar_release, epoch);
        } else {
            while (ld_acquire(&g_bar_release) < epoch) __nanosleep(32);
        }
    }
    __syncthreads();
}
__device__ __forceinline__ void mma_bf16(float* d, const uint32_t* a, const uint32_t* b) {
    asm volatile(
        "mma.sync.aligned.m16n8k16.row.col.f32.bf16.bf16.f32 "
        "{%0,%1,%2,%3}, {%4,%5,%6,%7}, {%8,%9}, {%0,%1,%2,%3};"
        : "+f"(d[0]), "+f"(d[1]), "+f"(d[2]), "+f"(d[3])
        : "r"(a[0]), "r"(a[1]), "r"(a[2]), "r"(a[3]), "r"(b[0]), "r"(b[1]));
}
__device__ __forceinline__ uint32_t pack_bf16(__nv_bfloat16 lo, __nv_bfloat16 hi) {
    uint32_t r;
    uint16_t l = *(uint16_t*)&lo, h = *(uint16_t*)&hi;
    r = ((uint32_t)h << 16) | l;
    return r;
}

// ---------------------------------------------------------------------------
// init: h = 0, c = 1 (reference inits c to ones), reset barrier
// ---------------------------------------------------------------------------
__global__ void k_init_state() {
    int i = blockIdx.x * blockDim.x + threadIdx.x;
    if (i < BATCH * UNITS) {
        g_h_hi[i] = __float2bfloat16(0.0f);
        g_h_lo[i] = __float2bfloat16(0.0f);
        g_c[i] = 1.0f;
    }
    if (i == 0) { g_bar_count = 0; g_bar_release = 0; }
}

// ---------------------------------------------------------------------------
// prep: split Wh into bf16 hi/lo and write mma-fragment-ordered per block.
// Fragment word (bx, term, mt, ks, lane, reg) holds WhT pair
//   g = gt*128 + mt*16 + lane/4 + (reg&1)*8
//   k = ksb*256 + ks*16 + 2*(lane%4) + (reg&2)*4   (pair k, k+1)
// ---------------------------------------------------------------------------
__global__ void __launch_bounds__(256) k_prep_frag(const float* __restrict__ Wh) {
    size_t t = (size_t)blockIdx.x * 256 + threadIdx.x;   // 0 .. 2^21-1
    int reg  = (int)(t & 3);
    int lane = (int)((t >> 2) & 31);
    int ks   = (int)((t >> 7) & 15);
    int mt   = (int)((t >> 11) & 7);
    int bx   = (int)(t >> 14);                            // 0..127

    int gt = bx & 31, ksb = bx >> 5;
    int r = lane >> 2, c = lane & 3;
    int gl = mt * 16 + r + (reg & 1) * 8;
    int kl = ks * 16 + 2 * c + (reg & 2) * 4;
    int gg = gt * GTILE + gl;
    int kg = ksb * KCH + kl;

    float x0 = __ldg(&Wh[(size_t)kg * GDIM + gg]);
    float x1 = __ldg(&Wh[(size_t)(kg + 1) * GDIM + gg]);

    __nv_bfloat16 h0 = __float2bfloat16(x0);
    __nv_bfloat16 h1 = __float2bfloat16(x1);
    __nv_bfloat16 l0 = __float2bfloat16(x0 - __bfloat162float(h0));
    __nv_bfloat16 l1 = __float2bfloat16(x1 - __bfloat162float(h1));

    size_t base = ((size_t)bx * 32768) + ((((size_t)mt * 16 + ks) * 32 + lane) * 4 + reg);
    g_wfrag[base]         = pack_bf16(h0, h1);
    g_wfrag[base + 16384] = pack_bf16(l0, l1);
}

// ---------------------------------------------------------------------------
// x-projection (unchanged): g_xg[t][b][g] = data[b][t][:] @ Wx[:,g] + bias[g]
// ---------------------------------------------------------------------------
__global__ void __launch_bounds__(256) k_xproj(const float* __restrict__ A,
                                               const float* __restrict__ Bw,
                                               const float* __restrict__ bias) {
    __shared__ float As[16][68];
    __shared__ float Bs[16][64];
    int n0 = blockIdx.x * 64;
    int m0 = blockIdx.y * 64;
    int tid = threadIdx.x;
    int tx = tid & 15, ty = tid >> 4;

    float acc[4][4];
#pragma unroll
    for (int i = 0; i < 4; i++)
#pragma unroll
        for (int j = 0; j < 4; j++) acc[i][j] = 0.0f;

    int la_k = tid & 15;
    int la_m = tid >> 4;
    int lb_n = tid & 63;
    int lb_k = tid >> 6;

    for (int k0 = 0; k0 < IND; k0 += 16) {
#pragma unroll
        for (int p = 0; p < 4; p++)
            As[la_k][la_m + p * 16] =
                A[(size_t)(m0 + la_m + p * 16) * IND + k0 + la_k];
#pragma unroll
        for (int p = 0; p < 4; p++)
            Bs[lb_k + p * 4][lb_n] =
                Bw[(size_t)(k0 + lb_k + p * 4) * GDIM + n0 + lb_n];
        __syncthreads();
#pragma unroll
        for (int k = 0; k < 16; k++) {
            float4 ra = *(const float4*)&As[k][ty * 4];
            float4 rb = *(const float4*)&Bs[k][tx * 4];
            float av[4] = {ra.x, ra.y, ra.z, ra.w};
            float bv[4] = {rb.x, rb.y, rb.z, rb.w};
#pragma unroll
            for (int i = 0; i < 4; i++)
#pragma unroll
                for (int j = 0; j < 4; j++) acc[i][j] += av[i] * bv[j];
        }
        __syncthreads();
    }

    int b  = m0 >> 9;
    int tb = (m0 & 511) + ty * 4;
    float4 bb4 = *(const float4*)&bias[n0 + tx * 4];
#pragma unroll
    for (int i = 0; i < 4; i++) {
        float4 v;
        v.x = acc[i][0] + bb4.x;
        v.y = acc[i][1] + bb4.y;
        v.z = acc[i][2] + bb4.z;
        v.w = acc[i][3] + bb4.w;
        *(float4*)&g_xg[(((size_t)(tb + i)) * BATCH + b) * GDIM + n0 + tx * 4] = v;
    }
}

// ---------------------------------------------------------------------------
// Persistent recurrence: 128 blocks x 128 threads, loops all 512 timesteps.
// Block (ksb, gt): partials for g in [gt*128,+128), K in [ksb*256,+256).
// Split bf16 mma.sync: Ah*Bh + Ah*Bl + Al*Bh (lo*lo dropped, ~2^-18 rel).
// ---------------------------------------------------------------------------
__global__ void __launch_bounds__(128, 1) k_persist(float* __restrict__ out) {
    extern __shared__ char smem[];
    uint32_t sb = smem_u32(smem);

    int tid = threadIdx.x;
    int wid = tid >> 5, lid = tid & 31;
    int bx = blockIdx.x;
    int ksb = bx >> 5;           // 0..3
    int gt  = bx & 31;           // 0..31
    int g0  = gt * GTILE;
    int koff = ksb * KCH;

    // ---- one-time: copy this block's Wh fragments into SMEM (128KB) ----
    {
        const uint4* src = (const uint4*)(g_wfrag + (size_t)bx * 32768);
        uint4* dst = (uint4*)smem;
        for (int i = tid; i < 8192; i += 128) dst[i] = src[i];
    }
    __syncthreads();

    const uint32_t* hh32 = (const uint32_t*)g_h_hi;
    const uint32_t* hl32 = (const uint32_t*)g_h_lo;

    // B-fill thread mapping
    int fb = tid >> 2;           // b 0..31
    int fq = tid & 3;            // k-quarter 0..3

    // pointwise mapping: this block owns u in [bx*8, bx*8+8)
    int pb = tid & 31;
    int pj = tid >> 5;

    for (int t = 0; t < SEQT; t++) {
        // ---- fill B fragments (h hi/lo) ----
        {
            const uint32_t* ph = hh32 + (((size_t)fb * UNITS + koff) >> 1) + fq * 32;
            const uint32_t* pl = hl32 + (((size_t)fb * UNITS + koff) >> 1) + fq * 32;
#pragma unroll 8
            for (int i = 0; i < 32; i++) {
                int k = fq * 64 + 2 * i;
                int lane_w = ((fb & 7) << 2) | ((k & 7) >> 1);
                int nt = fb >> 3, kst = k >> 4, j = (k >> 3) & 1;
                uint32_t off = ((((uint32_t)nt * 16 + kst) * 32 + lane_w) * 2 + j) * 4;
                *(uint32_t*)(smem + SM_B + off) = ph[i];
                *(uint32_t*)(smem + SM_B + SM_BTERM + off) = pl[i];
            }
        }
        __syncthreads();

        // ---- mma: 2 m-tiles x 4 n-tiles per warp, 16 k-steps, 3 terms ----
        float d[2][4][4];
#pragma unroll
        for (int i = 0; i < 2; i++)
#pragma unroll
            for (int nt = 0; nt < 4; nt++)
#pragma unroll
                for (int e = 0; e < 4; e++) d[i][nt][e] = 0.0f;

        for (int ks = 0; ks < 16; ks++) {
            uint32_t bh[4][2], bl[4][2];
#pragma unroll
            for (int nt = 0; nt < 4; nt++) {
                uint32_t ab = sb + SM_B + (((uint32_t)nt * 16 + ks) * 32 + lid) * 8;
                asm volatile("ld.shared.v2.u32 {%0,%1}, [%2];"
                             : "=r"(bh[nt][0]), "=r"(bh[nt][1]) : "r"(ab));
                asm volatile("ld.shared.v2.u32 {%0,%1}, [%2];"
                             : "=r"(bl[nt][0]), "=r"(bl[nt][1]) : "r"(ab + SM_BTERM));
            }
#pragma unroll
            for (int i = 0; i < 2; i++) {
                int mt = wid * 2 + i;
                uint32_t ah[4], al[4];
                uint32_t aa = sb + SM_A + (((uint32_t)mt * 16 + ks) * 32 + lid) * 16;
                asm volatile("ld.shared.v4.u32 {%0,%1,%2,%3}, [%4];"
                             : "=r"(ah[0]), "=r"(ah[1]), "=r"(ah[2]), "=r"(ah[3])
                             : "r"(aa));
                asm volatile("ld.shared.v4.u32 {%0,%1,%2,%3}, [%4];"
                             : "=r"(al[0]), "=r"(al[1]), "=r"(al[2]), "=r"(al[3])
                             : "r"(aa + SM_ATERM));
#pragma unroll
                for (int nt = 0; nt < 4; nt++) {
                    mma_bf16(d[i][nt], ah, bh[nt]);
                    mma_bf16(d[i][nt], ah, bl[nt]);
                    mma_bf16(d[i][nt], al, bh[nt]);
                }
            }
        }

        // ---- store partials: g_part[ksb][g][b] ----
        {
            int r = lid >> 2, c2 = (lid & 3) * 2;
            float* pp = g_part + ((size_t)ksb * GDIM + g0) * BATCH;
#pragma unroll
            for (int i = 0; i < 2; i++) {
                int gl = (wid * 2 + i) * 16 + r;
#pragma unroll
                for (int nt = 0; nt < 4; nt++) {
                    int bc = nt * 8 + c2;
                    float2 v0 = {d[i][nt][0], d[i][nt][1]};
                    float2 v1 = {d[i][nt][2], d[i][nt][3]};
                    *(float2*)&pp[(size_t)gl * BATCH + bc] = v0;
                    *(float2*)&pp[(size_t)(gl + 8) * BATCH + bc] = v1;
                }
            }
        }

        grid_bar(tid, 2 * (unsigned)t + 1);

        // ---- pointwise: u in [bx*8, bx*8+8), all 32 b ----
#pragma unroll
        for (int rr = 0; rr < 2; rr++) {
            int u = bx * 8 + pj + rr * 4;
            const float* xg = g_xg + ((size_t)t * BATCH + pb) * GDIM;
            float ai = xg[u];
            float af = xg[UNITS + u];
            float ag = xg[2 * UNITS + u];
            float ao = xg[3 * UNITS + u];
#pragma unroll
            for (int s = 0; s < KS_SPLIT; s++) {
                const float* p = g_part + ((size_t)s * GDIM) * BATCH + pb;
                ai += p[(size_t)u * BATCH];
                af += p[(size_t)(UNITS + u) * BATCH];
                ag += p[(size_t)(2 * UNITS + u) * BATCH];
                ao += p[(size_t)(3 * UNITS + u) * BATCH];
            }
            float ig = 1.0f / (1.0f + expf(-ai));
            float fg = 1.0f / (1.0f + expf(-af));
            float gg = tanhf(ag);
            float og = 1.0f / (1.0f + expf(-ao));

            int cu = pb * UNITS + u;
            float c = fg * g_c[cu] + ig * gg;
            g_c[cu] = c;
            float h = og * tanhf(c);

            out[((size_t)pb * SEQT + t) * UNITS + u] = h;
            __nv_bfloat16 hi = __float2bfloat16(h);
            g_h_hi[cu] = hi;
            g_h_lo[cu] = __float2bfloat16(h - __bfloat162float(hi));
        }

        grid_bar(tid, 2 * (unsigned)t + 2);
    }
}

// ---------------------------------------------------------------------------
// kernel_launch: 4 graph nodes.
// ---------------------------------------------------------------------------
extern "C" void kernel_launch(void* const* d_in, const int* in_sizes, int n_in,
                              void* d_out, int out_size) {
    (void)in_sizes; (void)n_in; (void)out_size;
    const float* data = (const float*)d_in[0];   // [32,512,512]
    const float* Wx   = (const float*)d_in[1];   // [512,4096]
    const float* Wh   = (const float*)d_in[2];   // [1024,4096]
    const float* bias = (const float*)d_in[3];   // [4096]
    float* out = (float*)d_out;                  // [32,512,1024]

    cudaFuncSetAttribute(k_persist, cudaFuncAttributeMaxDynamicSharedMemorySize,
                         SM_TOTAL);

    k_init_state<<<(BATCH * UNITS + 255) / 256, 256>>>();
    k_prep_frag<<<8192, 256>>>(Wh);
    k_xproj<<<dim3(GDIM / 64, MROWS / 64), 256>>>(data, Wx, bias);
    k_persist<<<NBLK, 128, SM_TOTAL>>>(out);
}